// round 3
// baseline (speedup 1.0000x reference)
#include <cuda_runtime.h>

// R3 resubmit: rounds 1-2 failed at container/broker level (no harness output);
// kernel unchanged from R2.

#define D_ELEMS   1048576
#define N_ROWS    50
#define TPB       256
#define CHUNKS    32
#define CHUNK_ELEMS (D_ELEMS / CHUNKS)   /* 32768 elems = 128 KB */
#define N4        (CHUNK_ELEMS / 4)      /* 8192 float4 per chunk */

__device__ float g_partials[N_ROWS * CHUNKS];

__global__ __launch_bounds__(TPB) void matvec_partial(
    const float* __restrict__ inp,
    const float* __restrict__ fc)
{
    const int row   = blockIdx.y;
    const int chunk = blockIdx.x;

    const float4* __restrict__ v = reinterpret_cast<const float4*>(
        inp + (size_t)chunk * CHUNK_ELEMS);
    const float4* __restrict__ m = reinterpret_cast<const float4*>(
        fc + (size_t)row * D_ELEMS + (size_t)chunk * CHUNK_ELEMS);

    float acc0 = 0.f, acc1 = 0.f, acc2 = 0.f, acc3 = 0.f;

    // 8192 float4 / 256 threads = 32 iters/thread; unroll x8 batches
    // up to 16 LDG.128 in flight per thread for MLP.
    #pragma unroll 8
    for (int i = threadIdx.x; i < N4; i += TPB) {
        float4 a = v[i];
        float4 b = m[i];
        acc0 = fmaf(a.x, b.x, acc0);
        acc1 = fmaf(a.y, b.y, acc1);
        acc2 = fmaf(a.z, b.z, acc2);
        acc3 = fmaf(a.w, b.w, acc3);
    }
    float acc = (acc0 + acc1) + (acc2 + acc3);

    // block reduction: warp shuffle then cross-warp via smem
    __shared__ float s[TPB / 32];
    #pragma unroll
    for (int o = 16; o > 0; o >>= 1)
        acc += __shfl_down_sync(0xffffffffu, acc, o);
    if ((threadIdx.x & 31) == 0)
        s[threadIdx.x >> 5] = acc;
    __syncthreads();
    if (threadIdx.x < TPB / 32) {
        acc = s[threadIdx.x];
        #pragma unroll
        for (int o = TPB / 64; o > 0; o >>= 1)
            acc += __shfl_down_sync(0xffu, acc, o);
        if (threadIdx.x == 0)
            g_partials[row * CHUNKS + chunk] = acc;
    }
}

__global__ void reduce_partials(float* __restrict__ out)
{
    const int row = threadIdx.x;
    if (row < N_ROWS) {
        float s = 0.f;
        #pragma unroll
        for (int c = 0; c < CHUNKS; c++)
            s += g_partials[row * CHUNKS + c];
        out[row] = s;
    }
}

extern "C" void kernel_launch(void* const* d_in, const int* in_sizes, int n_in,
                              void* d_out, int out_size)
{
    const float* inp = (const float*)d_in[0];   // [D]
    const float* fc  = (const float*)d_in[1];   // [N_ROWS, D]
    float* out = (float*)d_out;                 // [N_ROWS]

    dim3 grid(CHUNKS, N_ROWS);
    matvec_partial<<<grid, TPB>>>(inp, fc);
    reduce_partials<<<1, 64>>>(out);
}